// round 2
// baseline (speedup 1.0000x reference)
#include <cuda_runtime.h>

#define B_ 32
#define L_ 512
#define T_ 64

// CRF log-partition, linear-domain scan.
// alpha_j^t = lg[t,j] + log( sum_i exp(alpha_i^{t-1}) * E_ij ),  E = exp(trans)
// Maintain u_i = exp(alpha_i - K); per step: v = u @ E (f32x2 FMA),
// u' = v * exp(lg) * 2^{-e},  K += e*ln2  with e = exponent(u_old[0]) (exact).
__global__ __launch_bounds__(T_, 1) void crf_logz_kernel(
    const float* __restrict__ logits,
    const int* __restrict__ mask,
    const float* __restrict__ trans,
    float* __restrict__ out)
{
    const int b = blockIdx.x;
    const int j = threadIdx.x;

    __shared__ __align__(16) float ubuf[2][T_];
    __shared__ __align__(16) int msk[L_];
    __shared__ float red[2];

    // Preload this batch's mask row (512 int32 = 2KB): 64 threads x 2 int4.
    {
        const int4* msrc = (const int4*)(mask + (size_t)b * L_);
        int4* mdst = (int4*)msk;
        mdst[j] = msrc[j];
        mdst[j + 64] = msrc[j + 64];
    }

    // E[i][j] = exp(trans[i][j]); this thread's column, packed as f32x2 pairs.
    unsigned long long E2[T_ / 2];
    #pragma unroll
    for (int i = 0; i < T_; i += 2) {
        float e0 = __expf(trans[i * T_ + j]);
        float e1 = __expf(trans[(i + 1) * T_ + j]);
        asm("mov.b64 %0, {%1, %2};" : "=l"(E2[i / 2]) : "f"(e0), "f"(e1));
    }

    const float* lgb = logits + ((size_t)b * L_) * T_ + j;

    __syncthreads();  // msk visible

    // t = 0: alpha0 = logits[0,:] * mask0
    float m0 = (msk[0] != 0) ? 1.0f : 0.0f;
    ubuf[0][j] = __expf(lgb[0] * m0);

    int kexp = 0;  // accumulated power-of-two exponent (exact normalization)

    // software-pipelined logits loads, depth 2
    float lgA = lgb[1 * T_];
    float lgB = lgb[2 * T_];

    __syncthreads();

    int p = 0;
    for (int t = 1; t < L_; t++) {
        const float lg = lgA;
        lgA = lgB;
        if (t + 2 < L_) lgB = lgb[(t + 2) * T_];

        const float* up = ubuf[p];
        if (msk[t] != 0) {
            // v_j = sum_i u_i * E[i][j]   (broadcast LDS.128 + packed FFMA2)
            const ulonglong2* u2 = (const ulonglong2*)up;
            unsigned long long acc0 = 0ull, acc1 = 0ull, acc2 = 0ull, acc3 = 0ull;
            #pragma unroll
            for (int c = 0; c < 16; c += 2) {
                ulonglong2 qa = u2[c];
                asm("fma.rn.f32x2 %0, %1, %2, %0;" : "+l"(acc0) : "l"(qa.x), "l"(E2[2 * c]));
                asm("fma.rn.f32x2 %0, %1, %2, %0;" : "+l"(acc1) : "l"(qa.y), "l"(E2[2 * c + 1]));
                ulonglong2 qb = u2[c + 1];
                asm("fma.rn.f32x2 %0, %1, %2, %0;" : "+l"(acc2) : "l"(qb.x), "l"(E2[2 * c + 2]));
                asm("fma.rn.f32x2 %0, %1, %2, %0;" : "+l"(acc3) : "l"(qb.y), "l"(E2[2 * c + 3]));
            }
            float f0, f1, f2, f3, f4, f5, f6, f7;
            asm("mov.b64 {%0, %1}, %2;" : "=f"(f0), "=f"(f1) : "l"(acc0));
            asm("mov.b64 {%0, %1}, %2;" : "=f"(f2), "=f"(f3) : "l"(acc1));
            asm("mov.b64 {%0, %1}, %2;" : "=f"(f4), "=f"(f5) : "l"(acc2));
            asm("mov.b64 {%0, %1}, %2;" : "=f"(f6), "=f"(f7) : "l"(acc3));
            float v = ((f0 + f1) + (f2 + f3)) + ((f4 + f5) + (f6 + f7));

            // exact power-of-two renormalization by exponent of old u[0]
            float u0 = up[0];
            int e = ((__float_as_int(u0) >> 23) & 255) - 127;
            float scale = __int_as_float((127 - e) << 23);  // 2^{-e}
            kexp += e;
            ubuf[p ^ 1][j] = v * __expf(lg) * scale;
        } else {
            // masked step: exact identity (potentials = eye; off-diag exp(-1e4)
            // underflows to 0 in f32)
            ubuf[p ^ 1][j] = up[j];
        }
        p ^= 1;
        __syncthreads();
    }

    // out[b] = K + log(sum_j u_j)
    float s = ubuf[p][j];
    #pragma unroll
    for (int o = 16; o > 0; o >>= 1) s += __shfl_down_sync(0xffffffffu, s, o);
    if ((j & 31) == 0) red[j >> 5] = s;
    __syncthreads();
    if (j == 0)
        out[b] = (float)kexp * 0.6931471805599453f + __logf(red[0] + red[1]);
}

extern "C" void kernel_launch(void* const* d_in, const int* in_sizes, int n_in,
                              void* d_out, int out_size) {
    const float* logits = (const float*)d_in[0];  // (32,512,64) f32
    const int* mask     = (const int*)d_in[1];    // (32,512) bool -> int32
    const float* trans  = (const float*)d_in[2];  // (64,64) f32
    float* out          = (float*)d_out;          // (32,) f32
    (void)in_sizes; (void)n_in; (void)out_size;
    crf_logz_kernel<<<B_, T_>>>(logits, mask, trans, out);
}